// round 10
// baseline (speedup 1.0000x reference)
#include <cuda_runtime.h>
#include <cuda_fp16.h>
#include <mma.h>
#include <cstdint>

using namespace nvcuda;

#define N_NODES 100000
#define N_EDGES 20000
#define NNZ     1000000
#define IN_CH   128
#define OUT_DIM 64

#define RA 4                               // edge-cursor replicas
#define RB 2                               // node-cursor replicas
#define EBASE (N_EDGES * RA)               // 80000: start of node section
#define NC2   (N_EDGES * RA + N_NODES * RB) // 280000 scanned counters
#define SCAN_B 1024
#define NBLK  ((NC2 + SCAN_B - 1) / SCAN_B) // 274

// ---------------------------------------------------------------------------
// Device-global scratch (allocation-free per harness rules)
// ---------------------------------------------------------------------------
__device__ __align__(16) unsigned short g_Xl16[(size_t)N_NODES * OUT_DIM]; // 12.8 MB
__device__ __align__(16) unsigned short g_Xe16[(size_t)N_EDGES * OUT_DIM]; // 2.56 MB
__device__ int g_cnt[NC2];       // zeroed at end of each run by the gathers
__device__ int g_offp[NC2];
__device__ int g_bsum[NBLK];
__device__ int g_off[NC2 + 1];
__device__ int g_cur[NC2];
__device__ int g_permA[NNZ];     // bucketed by edge -> vertex id
__device__ int g_permB[NNZ];     // bucketed by node -> edge id

// ---------------------------------------------------------------------------
// CSR build with replicated cursors (R8-proven)
// ---------------------------------------------------------------------------
__global__ void k_hist(const int* __restrict__ vertex, const int* __restrict__ edges) {
    int i = blockIdx.x * blockDim.x + threadIdx.x;
    if (i >= NNZ) return;
    int w  = i >> 5;
    int ra = w & (RA - 1);
    int rb = w & (RB - 1);
    atomicAdd(&g_cnt[edges[i] * RA + ra], 1);
    atomicAdd(&g_cnt[EBASE + vertex[i] * RB + rb], 1);
}

__global__ __launch_bounds__(SCAN_B) void k_scan1() {
    __shared__ int s[SCAN_B];
    int t = threadIdx.x;
    int g = blockIdx.x * SCAN_B + t;
    int val = (g < NC2) ? g_cnt[g] : 0;
    s[t] = val;
    __syncthreads();
    int incl = val;
    #pragma unroll
    for (int d = 1; d < SCAN_B; d <<= 1) {
        int x = (t >= d) ? s[t - d] : 0;
        __syncthreads();
        incl += x;
        s[t] = incl;
        __syncthreads();
    }
    if (g < NC2) g_offp[g] = incl - val;
    if (t == SCAN_B - 1) g_bsum[blockIdx.x] = incl;
}

__global__ __launch_bounds__(SCAN_B) void k_scan23() {
    __shared__ int sl[32];
    const int t = threadIdx.x;
    const int b = blockIdx.x;

    int val = (t < NBLK && t < b) ? g_bsum[t] : 0;
    unsigned m = 0xffffffffu;
    #pragma unroll
    for (int o = 16; o > 0; o >>= 1) val += __shfl_down_sync(m, val, o);
    if ((t & 31) == 0) sl[t >> 5] = val;
    __syncthreads();
    if (t < 32) {
        int v = sl[t];
        #pragma unroll
        for (int o = 16; o > 0; o >>= 1) v += __shfl_down_sync(m, v, o);
        if (t == 0) sl[0] = v;
    }
    __syncthreads();
    const int prefix = sl[0];

    int g = b * SCAN_B + t;
    if (g < NC2) {
        int o = g_offp[g] + prefix;
        g_off[g] = o;
        g_cur[g] = o;
    }
    if (b == 0 && t == 0) g_off[NC2] = 2 * NNZ;
}

__global__ void k_fill(const int* __restrict__ vertex, const int* __restrict__ edges) {
    int i = blockIdx.x * blockDim.x + threadIdx.x;
    if (i >= NNZ) return;
    int w  = i >> 5;
    int ra = w & (RA - 1);
    int rb = w & (RB - 1);
    int e = edges[i];
    int v = vertex[i];
    int pA = atomicAdd(&g_cur[e * RA + ra], 1);
    g_permA[pA] = v;
    int pB = atomicAdd(&g_cur[EBASE + v * RB + rb], 1);
    g_permB[pB - NNZ] = e;
}

// ---------------------------------------------------------------------------
// GEMM via tensor cores (wmma m16n16k16, fp16 in, fp32 acc, fp16 out).
// Block 256 thr = 8 warps. Tile 128 rows x 64 cols; warp w owns rows 16w..16w+15
// and 4 accumulators covering all 64 cols. X staged fp16 in two 64-K chunks.
// Output staged through smem (aliases operand buffers) then stored fp16.
// ---------------------------------------------------------------------------
__global__ __launch_bounds__(256) void k_gemm(const float* __restrict__ X,
                                              const float* __restrict__ W) {
    __shared__ __align__(16) unsigned char sm[35840];
    __half* Xh = (__half*)sm;                 // [128][72] = 18432 B
    __half* Wh = (__half*)(sm + 18432);       // [128][64] = 16384 B
    float*  Of = (float*)sm;                  // [128][64] = 32768 B (phase 2 alias)

    const int tid  = threadIdx.x;
    const int wid  = tid >> 5;
    const int row0 = blockIdx.x * 128;
    const int r    = tid >> 1;                // staging row 0..127
    const int cb   = (tid & 1) * 32;          // staging col base 0 / 32

    // Stage all of W as fp16 (once)
    {
        const float4* src = (const float4*)(W + r * OUT_DIM + cb);
        __half* dst = Wh + r * 64 + cb;
        #pragma unroll
        for (int q = 0; q < 8; ++q) {
            float4 f = src[q];
            __half2 h0 = __floats2half2_rn(f.x, f.y);
            __half2 h1 = __floats2half2_rn(f.z, f.w);
            *(uint2*)(dst + q * 4) =
                make_uint2(*(unsigned*)&h0, *(unsigned*)&h1);
        }
    }

    wmma::fragment<wmma::accumulator, 16, 16, 16, float> acc[4];
    #pragma unroll
    for (int n = 0; n < 4; ++n) wmma::fill_fragment(acc[n], 0.0f);

    for (int kc = 0; kc < 2; ++kc) {
        __syncthreads();   // kc=0: covers Wh staging; kc=1: prior mma done with Xh
        // Stage X chunk [128 rows][64 k] -> fp16 transposed-none (row-major)
        {
            int grow = row0 + r;
            __half* dst = Xh + r * 72 + cb;
            if (grow < N_NODES) {
                const float4* src =
                    (const float4*)(X + (size_t)grow * IN_CH + kc * 64 + cb);
                #pragma unroll
                for (int q = 0; q < 8; ++q) {
                    float4 f = src[q];
                    __half2 h0 = __floats2half2_rn(f.x, f.y);
                    __half2 h1 = __floats2half2_rn(f.z, f.w);
                    *(uint2*)(dst + q * 4) =
                        make_uint2(*(unsigned*)&h0, *(unsigned*)&h1);
                }
            } else {
                #pragma unroll
                for (int q = 0; q < 8; ++q)
                    *(uint2*)(dst + q * 4) = make_uint2(0u, 0u);
            }
        }
        __syncthreads();

        #pragma unroll
        for (int kq = 0; kq < 4; ++kq) {
            wmma::fragment<wmma::matrix_a, 16, 16, 16, __half, wmma::row_major> af;
            wmma::load_matrix_sync(af, Xh + (16 * wid) * 72 + 16 * kq, 72);
            #pragma unroll
            for (int n = 0; n < 4; ++n) {
                wmma::fragment<wmma::matrix_b, 16, 16, 16, __half, wmma::row_major> bf;
                wmma::load_matrix_sync(bf, Wh + (kc * 64 + 16 * kq) * 64 + 16 * n, 64);
                wmma::mma_sync(acc[n], af, bf, acc[n]);
            }
        }
    }

    __syncthreads();   // all warps done reading Xh/Wh before aliasing as Of
    #pragma unroll
    for (int n = 0; n < 4; ++n)
        wmma::store_matrix_sync(Of + (16 * wid) * 64 + 16 * n, acc[n], 64,
                                wmma::mem_row_major);
    __syncthreads();

    // Convert Of (f32) -> g_Xl16 (fp16)
    {
        int grow = row0 + r;
        if (grow < N_NODES) {
            const float4* src = (const float4*)(Of + r * 64 + cb);
            unsigned short* dst = g_Xl16 + (size_t)grow * OUT_DIM + cb;
            #pragma unroll
            for (int q = 0; q < 8; ++q) {
                float4 f = src[q];
                __half2 h0 = __floats2half2_rn(f.x, f.y);
                __half2 h1 = __floats2half2_rn(f.z, f.w);
                *(uint2*)(dst + q * 4) =
                    make_uint2(*(unsigned*)&h0, *(unsigned*)&h1);
            }
        }
    }
}

// ---------------------------------------------------------------------------
// Gather 1: Xe[e] = (sum Xl[v]) * degE[e] * W_edge[e].  fp16 in/out, fp32 acc.
// ---------------------------------------------------------------------------
__global__ __launch_bounds__(256) void k_gatherA(const float* __restrict__ degE,
                                                 const float* __restrict__ W_edge) {
    int t = blockIdx.x * blockDim.x + threadIdx.x;
    int e = t >> 3;
    if (e >= N_EDGES) return;
    int lane = t & 7;
    int c = lane << 3;

    if (lane < RA) g_cnt[e * RA + lane] = 0;   // reset for next replay

    int beg = g_off[e * RA];
    int end = g_off[(e + 1) * RA];

    float a0 = 0.f, a1 = 0.f, a2 = 0.f, a3 = 0.f;
    float a4 = 0.f, a5 = 0.f, a6 = 0.f, a7 = 0.f;
    #pragma unroll 4
    for (int j = beg; j < end; ++j) {
        int v = __ldg(&g_permA[j]);
        uint4 u = *(const uint4*)(g_Xl16 + (size_t)v * OUT_DIM + c);
        float2 f0 = __half22float2(*reinterpret_cast<__half2*>(&u.x));
        float2 f1 = __half22float2(*reinterpret_cast<__half2*>(&u.y));
        float2 f2 = __half22float2(*reinterpret_cast<__half2*>(&u.z));
        float2 f3 = __half22float2(*reinterpret_cast<__half2*>(&u.w));
        a0 += f0.x; a1 += f0.y; a2 += f1.x; a3 += f1.y;
        a4 += f2.x; a5 += f2.y; a6 += f3.x; a7 += f3.y;
    }
    float s = degE[e] * W_edge[e];
    __half2 h0 = __floats2half2_rn(a0 * s, a1 * s);
    __half2 h1 = __floats2half2_rn(a2 * s, a3 * s);
    __half2 h2 = __floats2half2_rn(a4 * s, a5 * s);
    __half2 h3 = __floats2half2_rn(a6 * s, a7 * s);
    uint4 o;
    o.x = *reinterpret_cast<unsigned*>(&h0);
    o.y = *reinterpret_cast<unsigned*>(&h1);
    o.z = *reinterpret_cast<unsigned*>(&h2);
    o.w = *reinterpret_cast<unsigned*>(&h3);
    *(uint4*)(g_Xe16 + (size_t)e * OUT_DIM + c) = o;
}

// ---------------------------------------------------------------------------
// Gather 2: out[v] = (sum Xe[e]) * degV[v].  fp16 in, fp32 out.
// ---------------------------------------------------------------------------
__global__ __launch_bounds__(256) void k_gatherB(const float* __restrict__ degV,
                                                 float* __restrict__ out) {
    int t = blockIdx.x * blockDim.x + threadIdx.x;
    int v = t >> 3;
    if (v >= N_NODES) return;
    int lane = t & 7;
    int c = lane << 3;

    if (lane < RB) g_cnt[EBASE + v * RB + lane] = 0;   // reset for next replay

    int beg = g_off[EBASE + v * RB] - NNZ;
    int end = g_off[EBASE + (v + 1) * RB] - NNZ;

    float a0 = 0.f, a1 = 0.f, a2 = 0.f, a3 = 0.f;
    float a4 = 0.f, a5 = 0.f, a6 = 0.f, a7 = 0.f;
    #pragma unroll 4
    for (int j = beg; j < end; ++j) {
        int e = __ldg(&g_permB[j]);
        uint4 u = *(const uint4*)(g_Xe16 + (size_t)e * OUT_DIM + c);
        float2 f0 = __half22float2(*reinterpret_cast<__half2*>(&u.x));
        float2 f1 = __half22float2(*reinterpret_cast<__half2*>(&u.y));
        float2 f2 = __half22float2(*reinterpret_cast<__half2*>(&u.z));
        float2 f3 = __half22float2(*reinterpret_cast<__half2*>(&u.w));
        a0 += f0.x; a1 += f0.y; a2 += f1.x; a3 += f1.y;
        a4 += f2.x; a5 += f2.y; a6 += f3.x; a7 += f3.y;
    }
    float s = degV[v];
    float* dst = out + (size_t)v * OUT_DIM + c;
    *(float4*)dst       = make_float4(a0 * s, a1 * s, a2 * s, a3 * s);
    *(float4*)(dst + 4) = make_float4(a4 * s, a5 * s, a6 * s, a7 * s);
}

// ---------------------------------------------------------------------------
extern "C" void kernel_launch(void* const* d_in, const int* in_sizes, int n_in,
                              void* d_out, int out_size) {
    const float* X      = (const float*)d_in[0];
    const int*   vertex = (const int*)d_in[1];
    const int*   edges  = (const int*)d_in[2];
    const float* W_lin  = (const float*)d_in[3];
    const float* degE   = (const float*)d_in[4];
    const float* degV   = (const float*)d_in[5];
    const float* W_edge = (const float*)d_in[6];
    float*       out    = (float*)d_out;

    // g_cnt starts zeroed (static init on first run; gathers re-zero it each
    // run so every graph replay sees zeros — identical work every call).
    k_hist<<<(NNZ + 255) / 256, 256>>>(vertex, edges);
    k_scan1<<<NBLK, SCAN_B>>>();
    k_scan23<<<NBLK, SCAN_B>>>();
    k_fill<<<(NNZ + 255) / 256, 256>>>(vertex, edges);
    k_gemm<<<(N_NODES + 127) / 128, 256>>>(X, W_lin);
    k_gatherA<<<(N_EDGES * 8 + 255) / 256, 256>>>(degE, W_edge);
    k_gatherB<<<(N_NODES * 8 + 255) / 256, 256>>>(degV, out);
}

// round 11
// speedup vs baseline: 1.1132x; 1.1132x over previous
#include <cuda_runtime.h>
#include <cuda_fp16.h>
#include <cstdint>

#define N_NODES 100000
#define N_EDGES 20000
#define NNZ     1000000
#define IN_CH   128
#define OUT_DIM 64

#define RA 4                               // edge-cursor replicas
#define RB 2                               // node-cursor replicas
#define EBASE (N_EDGES * RA)               // 80000: start of node section
#define NC2   (N_EDGES * RA + N_NODES * RB) // 280000 scanned counters
#define SCAN_B 1024
#define NBLK  ((NC2 + SCAN_B - 1) / SCAN_B) // 274

// ---------------------------------------------------------------------------
// Device-global scratch (allocation-free per harness rules)
// ---------------------------------------------------------------------------
__device__ __align__(16) unsigned short g_Xl16[(size_t)N_NODES * OUT_DIM]; // 12.8 MB
__device__ __align__(16) unsigned short g_Xe16[(size_t)N_EDGES * OUT_DIM]; // 2.56 MB
__device__ int g_cnt[NC2];       // zeroed at end of each run by the gathers
__device__ int g_offp[NC2];
__device__ int g_bsum[NBLK];
__device__ int g_off[NC2 + 1];
__device__ int g_rankA[NNZ];     // ticket within edge bucket (from hist atomic)
__device__ int g_rankB[NNZ];     // ticket within node bucket
__device__ int g_permA[NNZ];     // bucketed by edge -> vertex id
__device__ int g_permB[NNZ];     // bucketed by node -> edge id

// ---------------------------------------------------------------------------
// Histogram + ticket assignment: the atomicAdd return value IS the rank.
// ---------------------------------------------------------------------------
__global__ void k_hist(const int* __restrict__ vertex, const int* __restrict__ edges) {
    int i = blockIdx.x * blockDim.x + threadIdx.x;
    if (i >= NNZ) return;
    int w  = i >> 5;
    int ra = w & (RA - 1);
    int rb = w & (RB - 1);
    g_rankA[i] = atomicAdd(&g_cnt[edges[i] * RA + ra], 1);
    g_rankB[i] = atomicAdd(&g_cnt[EBASE + vertex[i] * RB + rb], 1);
}

// Warp-shuffle block scan (exclusive partials + block sums).
__global__ __launch_bounds__(SCAN_B) void k_scan1() {
    __shared__ int wsum[32];
    const int t = threadIdx.x;
    const int g = blockIdx.x * SCAN_B + t;
    const int lane = t & 31;
    const int w = t >> 5;

    int val = (g < NC2) ? g_cnt[g] : 0;
    int incl = val;
    #pragma unroll
    for (int d = 1; d < 32; d <<= 1) {
        int x = __shfl_up_sync(0xffffffffu, incl, d);
        if (lane >= d) incl += x;
    }
    if (lane == 31) wsum[w] = incl;
    __syncthreads();
    if (w == 0) {
        int s = wsum[lane];
        #pragma unroll
        for (int d = 1; d < 32; d <<= 1) {
            int x = __shfl_up_sync(0xffffffffu, s, d);
            if (lane >= d) s += x;
        }
        wsum[lane] = s;
    }
    __syncthreads();
    int prefix = (w > 0) ? wsum[w - 1] : 0;
    if (g < NC2) g_offp[g] = prefix + incl - val;
    if (t == SCAN_B - 1) g_bsum[blockIdx.x] = prefix + incl;
}

// Fused scan2+scan3: each block reduces the block-aggregate prefix itself.
__global__ __launch_bounds__(SCAN_B) void k_scan23() {
    __shared__ int sl[32];
    const int t = threadIdx.x;
    const int b = blockIdx.x;

    int val = (t < NBLK && t < b) ? g_bsum[t] : 0;
    unsigned m = 0xffffffffu;
    #pragma unroll
    for (int o = 16; o > 0; o >>= 1) val += __shfl_down_sync(m, val, o);
    if ((t & 31) == 0) sl[t >> 5] = val;
    __syncthreads();
    if (t < 32) {
        int v = sl[t];
        #pragma unroll
        for (int o = 16; o > 0; o >>= 1) v += __shfl_down_sync(m, v, o);
        if (t == 0) sl[0] = v;
    }
    __syncthreads();
    const int prefix = sl[0];

    int g = b * SCAN_B + t;
    if (g < NC2) g_off[g] = g_offp[g] + prefix;
    if (b == 0 && t == 0) g_off[NC2] = 2 * NNZ;
}

// Atomic-free placement: pos = off[bucket] + precomputed rank.
__global__ void k_fill(const int* __restrict__ vertex, const int* __restrict__ edges) {
    int i = blockIdx.x * blockDim.x + threadIdx.x;
    if (i >= NNZ) return;
    int w  = i >> 5;
    int ra = w & (RA - 1);
    int rb = w & (RB - 1);
    int e = edges[i];
    int v = vertex[i];
    int pA = g_off[e * RA + ra] + g_rankA[i];
    g_permA[pA] = v;
    int pB = g_off[EBASE + v * RB + rb] + g_rankB[i] - NNZ;
    g_permB[pB] = e;
}

// ---------------------------------------------------------------------------
// GEMM (R4-proven): Xl[N,64] = X[N,128] @ W[128,64], fp32 compute, fp16 store.
// Launched at index 3 so the profiler (captures launch #3) finally shows it.
// ---------------------------------------------------------------------------
__global__ __launch_bounds__(256) void k_gemm(const float* __restrict__ X,
                                              const float* __restrict__ W) {
    __shared__ float Ws[IN_CH][OUT_DIM];
    __shared__ float Xs[32][68];

    const int tid  = threadIdx.x;
    const int row0 = blockIdx.x * 64;

    {
        const float4* W4  = (const float4*)W;
        float4*       Ws4 = (float4*)&Ws[0][0];
        #pragma unroll
        for (int i = tid; i < IN_CH * OUT_DIM / 4; i += 256) Ws4[i] = W4[i];
    }

    const int tx = tid & 15;
    const int ty = tid >> 4;

    float acc[4][4];
    #pragma unroll
    for (int i = 0; i < 4; ++i)
        #pragma unroll
        for (int j = 0; j < 4; ++j) acc[i][j] = 0.0f;

    const int lr  = tid >> 3;
    const int lkf = tid & 7;

    for (int kc = 0; kc < 4; ++kc) {
        __syncthreads();
        #pragma unroll
        for (int j = 0; j < 2; ++j) {
            int r    = lr + 32 * j;
            int grow = row0 + r;
            float4 x = make_float4(0.f, 0.f, 0.f, 0.f);
            if (grow < N_NODES)
                x = *(const float4*)(X + (size_t)grow * IN_CH + kc * 32 + lkf * 4);
            Xs[lkf * 4 + 0][r] = x.x;
            Xs[lkf * 4 + 1][r] = x.y;
            Xs[lkf * 4 + 2][r] = x.z;
            Xs[lkf * 4 + 3][r] = x.w;
        }
        __syncthreads();

        #pragma unroll
        for (int k = 0; k < 32; ++k) {
            float4 a = *(const float4*)&Xs[k][4 * ty];
            float4 b = *(const float4*)&Ws[kc * 32 + k][4 * tx];
            acc[0][0] += a.x * b.x; acc[0][1] += a.x * b.y;
            acc[0][2] += a.x * b.z; acc[0][3] += a.x * b.w;
            acc[1][0] += a.y * b.x; acc[1][1] += a.y * b.y;
            acc[1][2] += a.y * b.z; acc[1][3] += a.y * b.w;
            acc[2][0] += a.z * b.x; acc[2][1] += a.z * b.y;
            acc[2][2] += a.z * b.z; acc[2][3] += a.z * b.w;
            acc[3][0] += a.w * b.x; acc[3][1] += a.w * b.y;
            acc[3][2] += a.w * b.z; acc[3][3] += a.w * b.w;
        }
    }

    #pragma unroll
    for (int i = 0; i < 4; ++i) {
        int grow = row0 + 4 * ty + i;
        if (grow < N_NODES) {
            __half2 h01 = __floats2half2_rn(acc[i][0], acc[i][1]);
            __half2 h23 = __floats2half2_rn(acc[i][2], acc[i][3]);
            uint2 u = make_uint2(*reinterpret_cast<unsigned*>(&h01),
                                 *reinterpret_cast<unsigned*>(&h23));
            *(uint2*)(g_Xl16 + (size_t)grow * OUT_DIM + 4 * tx) = u;
        }
    }
}

// ---------------------------------------------------------------------------
// Gather 1: Xe[e] = (sum Xl[v]) * degE[e] * W_edge[e].  fp16 in/out, fp32 acc.
// ---------------------------------------------------------------------------
__global__ __launch_bounds__(256) void k_gatherA(const float* __restrict__ degE,
                                                 const float* __restrict__ W_edge) {
    int t = blockIdx.x * blockDim.x + threadIdx.x;
    int e = t >> 3;
    if (e >= N_EDGES) return;
    int lane = t & 7;
    int c = lane << 3;

    if (lane < RA) g_cnt[e * RA + lane] = 0;   // reset for next replay

    int beg = g_off[e * RA];
    int end = g_off[(e + 1) * RA];

    float a0 = 0.f, a1 = 0.f, a2 = 0.f, a3 = 0.f;
    float a4 = 0.f, a5 = 0.f, a6 = 0.f, a7 = 0.f;
    #pragma unroll 4
    for (int j = beg; j < end; ++j) {
        int v = __ldg(&g_permA[j]);
        uint4 u = *(const uint4*)(g_Xl16 + (size_t)v * OUT_DIM + c);
        float2 f0 = __half22float2(*reinterpret_cast<__half2*>(&u.x));
        float2 f1 = __half22float2(*reinterpret_cast<__half2*>(&u.y));
        float2 f2 = __half22float2(*reinterpret_cast<__half2*>(&u.z));
        float2 f3 = __half22float2(*reinterpret_cast<__half2*>(&u.w));
        a0 += f0.x; a1 += f0.y; a2 += f1.x; a3 += f1.y;
        a4 += f2.x; a5 += f2.y; a6 += f3.x; a7 += f3.y;
    }
    float s = degE[e] * W_edge[e];
    __half2 h0 = __floats2half2_rn(a0 * s, a1 * s);
    __half2 h1 = __floats2half2_rn(a2 * s, a3 * s);
    __half2 h2 = __floats2half2_rn(a4 * s, a5 * s);
    __half2 h3 = __floats2half2_rn(a6 * s, a7 * s);
    uint4 o;
    o.x = *reinterpret_cast<unsigned*>(&h0);
    o.y = *reinterpret_cast<unsigned*>(&h1);
    o.z = *reinterpret_cast<unsigned*>(&h2);
    o.w = *reinterpret_cast<unsigned*>(&h3);
    *(uint4*)(g_Xe16 + (size_t)e * OUT_DIM + c) = o;
}

// ---------------------------------------------------------------------------
// Gather 2: out[v] = (sum Xe[e]) * degV[v].  fp16 in, fp32 out.
// ---------------------------------------------------------------------------
__global__ __launch_bounds__(256) void k_gatherB(const float* __restrict__ degV,
                                                 float* __restrict__ out) {
    int t = blockIdx.x * blockDim.x + threadIdx.x;
    int v = t >> 3;
    if (v >= N_NODES) return;
    int lane = t & 7;
    int c = lane << 3;

    if (lane < RB) g_cnt[EBASE + v * RB + lane] = 0;   // reset for next replay

    int beg = g_off[EBASE + v * RB] - NNZ;
    int end = g_off[EBASE + (v + 1) * RB] - NNZ;

    float a0 = 0.f, a1 = 0.f, a2 = 0.f, a3 = 0.f;
    float a4 = 0.f, a5 = 0.f, a6 = 0.f, a7 = 0.f;
    #pragma unroll 4
    for (int j = beg; j < end; ++j) {
        int e = __ldg(&g_permB[j]);
        uint4 u = *(const uint4*)(g_Xe16 + (size_t)e * OUT_DIM + c);
        float2 f0 = __half22float2(*reinterpret_cast<__half2*>(&u.x));
        float2 f1 = __half22float2(*reinterpret_cast<__half2*>(&u.y));
        float2 f2 = __half22float2(*reinterpret_cast<__half2*>(&u.z));
        float2 f3 = __half22float2(*reinterpret_cast<__half2*>(&u.w));
        a0 += f0.x; a1 += f0.y; a2 += f1.x; a3 += f1.y;
        a4 += f2.x; a5 += f2.y; a6 += f3.x; a7 += f3.y;
    }
    float s = degV[v];
    float* dst = out + (size_t)v * OUT_DIM + c;
    *(float4*)dst       = make_float4(a0 * s, a1 * s, a2 * s, a3 * s);
    *(float4*)(dst + 4) = make_float4(a4 * s, a5 * s, a6 * s, a7 * s);
}

// ---------------------------------------------------------------------------
extern "C" void kernel_launch(void* const* d_in, const int* in_sizes, int n_in,
                              void* d_out, int out_size) {
    const float* X      = (const float*)d_in[0];
    const int*   vertex = (const int*)d_in[1];
    const int*   edges  = (const int*)d_in[2];
    const float* W_lin  = (const float*)d_in[3];
    const float* degE   = (const float*)d_in[4];
    const float* degV   = (const float*)d_in[5];
    const float* W_edge = (const float*)d_in[6];
    float*       out    = (float*)d_out;

    // g_cnt starts zeroed (static init on first run; gathers re-zero it each
    // run so every graph replay sees zeros — identical work every call).
    // Launch order puts k_gemm at index 3 (the profiler's capture slot).
    k_hist<<<(NNZ + 255) / 256, 256>>>(vertex, edges);
    k_scan1<<<NBLK, SCAN_B>>>();
    k_scan23<<<NBLK, SCAN_B>>>();
    k_gemm<<<(N_NODES + 63) / 64, 256>>>(X, W_lin);
    k_fill<<<(NNZ + 255) / 256, 256>>>(vertex, edges);
    k_gatherA<<<(N_EDGES * 8 + 255) / 256, 256>>>(degE, W_edge);
    k_gatherB<<<(N_NODES * 8 + 255) / 256, 256>>>(degV, out);
}

// round 12
// speedup vs baseline: 1.4131x; 1.2694x over previous
#include <cuda_runtime.h>
#include <cuda_fp16.h>
#include <mma.h>
#include <cstdint>

using namespace nvcuda;

#define N_NODES 100000
#define N_EDGES 20000
#define NNZ     1000000
#define IN_CH   128
#define OUT_DIM 64

#define RA 4                               // edge-cursor replicas
#define RB 2                               // node-cursor replicas
#define EBASE (N_EDGES * RA)               // 80000: start of node section
#define NC2   (N_EDGES * RA + N_NODES * RB) // 280000 scanned counters
#define SCAN_B 1024
#define NBLK  ((NC2 + SCAN_B - 1) / SCAN_B) // 274

// ---------------------------------------------------------------------------
// Device-global scratch (allocation-free per harness rules)
// ---------------------------------------------------------------------------
__device__ __align__(16) unsigned short g_Xl16[(size_t)N_NODES * OUT_DIM]; // 12.8 MB
__device__ __align__(16) unsigned short g_Xe16[(size_t)N_EDGES * OUT_DIM]; // 2.56 MB
__device__ int g_cnt[NC2];       // zeroed at end of each run by the gathers
__device__ int g_offp[NC2];
__device__ int g_bsum[NBLK];
__device__ int g_off[NC2 + 1];
__device__ int g_rankA[NNZ];     // ticket within edge bucket (from hist atomic)
__device__ int g_rankB[NNZ];     // ticket within node bucket
__device__ int g_permA[NNZ];     // bucketed by edge -> vertex id
__device__ int g_permB[NNZ];     // bucketed by node -> edge id

// ---------------------------------------------------------------------------
// Histogram + ticket assignment: the atomicAdd return value IS the rank.
// ---------------------------------------------------------------------------
__global__ void k_hist(const int* __restrict__ vertex, const int* __restrict__ edges) {
    int i = blockIdx.x * blockDim.x + threadIdx.x;
    if (i >= NNZ) return;
    int w  = i >> 5;
    int ra = w & (RA - 1);
    int rb = w & (RB - 1);
    g_rankA[i] = atomicAdd(&g_cnt[edges[i] * RA + ra], 1);
    g_rankB[i] = atomicAdd(&g_cnt[EBASE + vertex[i] * RB + rb], 1);
}

// Warp-shuffle block scan (exclusive partials + block sums).
__global__ __launch_bounds__(SCAN_B) void k_scan1() {
    __shared__ int wsum[32];
    const int t = threadIdx.x;
    const int g = blockIdx.x * SCAN_B + t;
    const int lane = t & 31;
    const int w = t >> 5;

    int val = (g < NC2) ? g_cnt[g] : 0;
    int incl = val;
    #pragma unroll
    for (int d = 1; d < 32; d <<= 1) {
        int x = __shfl_up_sync(0xffffffffu, incl, d);
        if (lane >= d) incl += x;
    }
    if (lane == 31) wsum[w] = incl;
    __syncthreads();
    if (w == 0) {
        int s = wsum[lane];
        #pragma unroll
        for (int d = 1; d < 32; d <<= 1) {
            int x = __shfl_up_sync(0xffffffffu, s, d);
            if (lane >= d) s += x;
        }
        wsum[lane] = s;
    }
    __syncthreads();
    int prefix = (w > 0) ? wsum[w - 1] : 0;
    if (g < NC2) g_offp[g] = prefix + incl - val;
    if (t == SCAN_B - 1) g_bsum[blockIdx.x] = prefix + incl;
}

// Fused scan2+scan3: each block reduces the block-aggregate prefix itself.
__global__ __launch_bounds__(SCAN_B) void k_scan23() {
    __shared__ int sl[32];
    const int t = threadIdx.x;
    const int b = blockIdx.x;

    int val = (t < NBLK && t < b) ? g_bsum[t] : 0;
    unsigned m = 0xffffffffu;
    #pragma unroll
    for (int o = 16; o > 0; o >>= 1) val += __shfl_down_sync(m, val, o);
    if ((t & 31) == 0) sl[t >> 5] = val;
    __syncthreads();
    if (t < 32) {
        int v = sl[t];
        #pragma unroll
        for (int o = 16; o > 0; o >>= 1) v += __shfl_down_sync(m, v, o);
        if (t == 0) sl[0] = v;
    }
    __syncthreads();
    const int prefix = sl[0];

    int g = b * SCAN_B + t;
    if (g < NC2) g_off[g] = g_offp[g] + prefix;
    if (b == 0 && t == 0) g_off[NC2] = 2 * NNZ;
}

// Atomic-free placement: pos = off[bucket] + precomputed rank.
__global__ void k_fill(const int* __restrict__ vertex, const int* __restrict__ edges) {
    int i = blockIdx.x * blockDim.x + threadIdx.x;
    if (i >= NNZ) return;
    int w  = i >> 5;
    int ra = w & (RA - 1);
    int rb = w & (RB - 1);
    int e = edges[i];
    int v = vertex[i];
    int pA = g_off[e * RA + ra] + g_rankA[i];
    g_permA[pA] = v;
    int pB = g_off[EBASE + v * RB + rb] + g_rankB[i] - NNZ;
    g_permB[pB] = e;
}

// ---------------------------------------------------------------------------
// GEMM via tensor cores (wmma m16n16k16, fp16 in, fp32 acc, fp16 out).
// Tile 64 rows x 64 cols per 256-thr block. All K=128 staged once (1 sync).
// Padded strides (136 / 72 halves) -> conflict-free ldsm. Warp (s, h):
// s = wid>>1 owns rows 16s..16s+15, h = wid&1 owns cols 32h..32h+31 (2 frags).
// ---------------------------------------------------------------------------
__global__ __launch_bounds__(256) void k_gemm(const float* __restrict__ X,
                                              const float* __restrict__ W) {
    __shared__ __align__(16) unsigned char sm[35840];
    __half* Xh = (__half*)sm;                 // [64][136] = 17408 B
    __half* Wh = (__half*)(sm + 17408);       // [128][72] = 18432 B
    float*  Of = (float*)sm;                  // [64][64]  = 16384 B (alias, phase 2)

    const int tid  = threadIdx.x;
    const int wid  = tid >> 5;
    const int row0 = blockIdx.x * 64;

    // Stage X tile (64 rows x 128 k) as fp16. 4 threads/row, 64B runs.
    {
        int r    = tid >> 2;
        int l4   = tid & 3;
        int grow = row0 + r;
        const float4* src = (const float4*)(X + (size_t)grow * IN_CH);
        __half* dst = Xh + r * 136;
        #pragma unroll
        for (int q = 0; q < 8; ++q) {
            int idx = q * 4 + l4;             // float4 index 0..31
            float4 f = make_float4(0.f, 0.f, 0.f, 0.f);
            if (grow < N_NODES) f = src[idx];
            __half2 h0 = __floats2half2_rn(f.x, f.y);
            __half2 h1 = __floats2half2_rn(f.z, f.w);
            *(uint2*)(dst + idx * 4) = make_uint2(*(unsigned*)&h0, *(unsigned*)&h1);
        }
    }
    // Stage W (128 x 64) as fp16: 2048 float4, 8 per thread.
    {
        const float4* W4 = (const float4*)W;
        #pragma unroll
        for (int q = 0; q < 8; ++q) {
            int idx = tid + q * 256;          // 0..2047
            int r   = idx >> 4;
            int c4  = idx & 15;
            float4 f = W4[idx];
            __half2 h0 = __floats2half2_rn(f.x, f.y);
            __half2 h1 = __floats2half2_rn(f.z, f.w);
            *(uint2*)(Wh + r * 72 + c4 * 4) =
                make_uint2(*(unsigned*)&h0, *(unsigned*)&h1);
        }
    }
    __syncthreads();

    const int s = wid >> 1;                   // row strip 0..3
    const int h = wid & 1;                    // col half 0..1

    wmma::fragment<wmma::accumulator, 16, 16, 16, float> acc[2];
    wmma::fill_fragment(acc[0], 0.0f);
    wmma::fill_fragment(acc[1], 0.0f);

    #pragma unroll
    for (int kq = 0; kq < 8; ++kq) {
        wmma::fragment<wmma::matrix_a, 16, 16, 16, __half, wmma::row_major> af;
        wmma::load_matrix_sync(af, Xh + (16 * s) * 136 + 16 * kq, 136);
        #pragma unroll
        for (int j = 0; j < 2; ++j) {
            wmma::fragment<wmma::matrix_b, 16, 16, 16, __half, wmma::row_major> bf;
            wmma::load_matrix_sync(bf, Wh + (16 * kq) * 72 + (32 * h + 16 * j), 72);
            wmma::mma_sync(acc[j], af, bf, acc[j]);
        }
    }

    __syncthreads();   // all reads of Xh done before aliasing as Of
    wmma::store_matrix_sync(Of + (16 * s) * 64 + 32 * h,      acc[0], 64,
                            wmma::mem_row_major);
    wmma::store_matrix_sync(Of + (16 * s) * 64 + 32 * h + 16, acc[1], 64,
                            wmma::mem_row_major);
    __syncthreads();

    // Convert Of (f32) -> g_Xl16 (fp16). 4 threads/row, 16 cols each.
    {
        int r    = tid >> 2;
        int cb   = (tid & 3) * 16;
        int grow = row0 + r;
        if (grow < N_NODES) {
            const float4* src = (const float4*)(Of + r * 64 + cb);
            unsigned short* dst = g_Xl16 + (size_t)grow * OUT_DIM + cb;
            #pragma unroll
            for (int q = 0; q < 4; ++q) {
                float4 f = src[q];
                __half2 h0 = __floats2half2_rn(f.x, f.y);
                __half2 h1 = __floats2half2_rn(f.z, f.w);
                *(uint2*)(dst + q * 4) =
                    make_uint2(*(unsigned*)&h0, *(unsigned*)&h1);
            }
        }
    }
}

// ---------------------------------------------------------------------------
// Gather 1: Xe[e] = (sum Xl[v]) * degE[e] * W_edge[e].  fp16 in/out, fp32 acc.
// ---------------------------------------------------------------------------
__global__ __launch_bounds__(256) void k_gatherA(const float* __restrict__ degE,
                                                 const float* __restrict__ W_edge) {
    int t = blockIdx.x * blockDim.x + threadIdx.x;
    int e = t >> 3;
    if (e >= N_EDGES) return;
    int lane = t & 7;
    int c = lane << 3;

    if (lane < RA) g_cnt[e * RA + lane] = 0;   // reset for next replay

    int beg = g_off[e * RA];
    int end = g_off[(e + 1) * RA];

    float a0 = 0.f, a1 = 0.f, a2 = 0.f, a3 = 0.f;
    float a4 = 0.f, a5 = 0.f, a6 = 0.f, a7 = 0.f;
    #pragma unroll 4
    for (int j = beg; j < end; ++j) {
        int v = __ldg(&g_permA[j]);
        uint4 u = *(const uint4*)(g_Xl16 + (size_t)v * OUT_DIM + c);
        float2 f0 = __half22float2(*reinterpret_cast<__half2*>(&u.x));
        float2 f1 = __half22float2(*reinterpret_cast<__half2*>(&u.y));
        float2 f2 = __half22float2(*reinterpret_cast<__half2*>(&u.z));
        float2 f3 = __half22float2(*reinterpret_cast<__half2*>(&u.w));
        a0 += f0.x; a1 += f0.y; a2 += f1.x; a3 += f1.y;
        a4 += f2.x; a5 += f2.y; a6 += f3.x; a7 += f3.y;
    }
    float s = degE[e] * W_edge[e];
    __half2 h0 = __floats2half2_rn(a0 * s, a1 * s);
    __half2 h1 = __floats2half2_rn(a2 * s, a3 * s);
    __half2 h2 = __floats2half2_rn(a4 * s, a5 * s);
    __half2 h3 = __floats2half2_rn(a6 * s, a7 * s);
    uint4 o;
    o.x = *reinterpret_cast<unsigned*>(&h0);
    o.y = *reinterpret_cast<unsigned*>(&h1);
    o.z = *reinterpret_cast<unsigned*>(&h2);
    o.w = *reinterpret_cast<unsigned*>(&h3);
    *(uint4*)(g_Xe16 + (size_t)e * OUT_DIM + c) = o;
}

// ---------------------------------------------------------------------------
// Gather 2: out[v] = (sum Xe[e]) * degV[v].  fp16 in, fp32 out.
// ---------------------------------------------------------------------------
__global__ __launch_bounds__(256) void k_gatherB(const float* __restrict__ degV,
                                                 float* __restrict__ out) {
    int t = blockIdx.x * blockDim.x + threadIdx.x;
    int v = t >> 3;
    if (v >= N_NODES) return;
    int lane = t & 7;
    int c = lane << 3;

    if (lane < RB) g_cnt[EBASE + v * RB + lane] = 0;   // reset for next replay

    int beg = g_off[EBASE + v * RB] - NNZ;
    int end = g_off[EBASE + (v + 1) * RB] - NNZ;

    float a0 = 0.f, a1 = 0.f, a2 = 0.f, a3 = 0.f;
    float a4 = 0.f, a5 = 0.f, a6 = 0.f, a7 = 0.f;
    #pragma unroll 4
    for (int j = beg; j < end; ++j) {
        int e = __ldg(&g_permB[j]);
        uint4 u = *(const uint4*)(g_Xe16 + (size_t)e * OUT_DIM + c);
        float2 f0 = __half22float2(*reinterpret_cast<__half2*>(&u.x));
        float2 f1 = __half22float2(*reinterpret_cast<__half2*>(&u.y));
        float2 f2 = __half22float2(*reinterpret_cast<__half2*>(&u.z));
        float2 f3 = __half22float2(*reinterpret_cast<__half2*>(&u.w));
        a0 += f0.x; a1 += f0.y; a2 += f1.x; a3 += f1.y;
        a4 += f2.x; a5 += f2.y; a6 += f3.x; a7 += f3.y;
    }
    float s = degV[v];
    float* dst = out + (size_t)v * OUT_DIM + c;
    *(float4*)dst       = make_float4(a0 * s, a1 * s, a2 * s, a3 * s);
    *(float4*)(dst + 4) = make_float4(a4 * s, a5 * s, a6 * s, a7 * s);
}

// ---------------------------------------------------------------------------
extern "C" void kernel_launch(void* const* d_in, const int* in_sizes, int n_in,
                              void* d_out, int out_size) {
    const float* X      = (const float*)d_in[0];
    const int*   vertex = (const int*)d_in[1];
    const int*   edges  = (const int*)d_in[2];
    const float* W_lin  = (const float*)d_in[3];
    const float* degE   = (const float*)d_in[4];
    const float* degV   = (const float*)d_in[5];
    const float* W_edge = (const float*)d_in[6];
    float*       out    = (float*)d_out;

    // g_cnt starts zeroed (static init on first run; gathers re-zero it each
    // run so every graph replay sees zeros — identical work every call).
    // k_gemm stays at launch index 3 (the profiler's capture slot).
    k_hist<<<(NNZ + 255) / 256, 256>>>(vertex, edges);
    k_scan1<<<NBLK, SCAN_B>>>();
    k_scan23<<<NBLK, SCAN_B>>>();
    k_gemm<<<(N_NODES + 63) / 64, 256>>>(X, W_lin);
    k_fill<<<(NNZ + 255) / 256, 256>>>(vertex, edges);
    k_gatherA<<<(N_EDGES * 8 + 255) / 256, 256>>>(degE, W_edge);
    k_gatherB<<<(N_NODES * 8 + 255) / 256, 256>>>(degV, out);
}